// round 2
// baseline (speedup 1.0000x reference)
#include <cuda_runtime.h>
#include <cstdint>

// Problem constants
#define B    4
#define C    96
#define C3   288
#define HH   256
#define WW   256
#define HWPIX 65536           // 256*256
#define HEADS 3
#define HC   32
#define OUT_ELEMS (B * C * HWPIX)     // 25165824

// ---------------- scratch (device globals; no runtime allocation) ----------------
__device__ float g_qkv[(size_t)B * C3 * HWPIX];  // post 1x1 conv (~302 MB)
__device__ float g_v  [(size_t)B * C  * HWPIX];  // post depthwise, v only (~100 MB)
__device__ float g_G  [B * HEADS * HC * HC];     // raw Gram q k^T
__device__ float g_qn [B * C];                   // sum q^2 per (b, q-channel)
__device__ float g_kn [B * C];
__device__ float g_M  [B * C * C];               // proj_w @ blockdiag(attn)

// ---------------- packed f32x2 helpers ----------------
typedef unsigned long long ull;

__device__ __forceinline__ ull pk2(float v) {
    ull r; asm("mov.b64 %0, {%1, %1};" : "=l"(r) : "f"(v)); return r;
}
__device__ __forceinline__ ull pack2(float lo, float hi) {
    ull r; asm("mov.b64 %0, {%1, %2};" : "=l"(r) : "f"(lo), "f"(hi)); return r;
}
__device__ __forceinline__ float2 unpk2(ull v) {
    float2 r; asm("mov.b64 {%0, %1}, %2;" : "=f"(r.x), "=f"(r.y) : "l"(v)); return r;
}
__device__ __forceinline__ ull fma2(ull a, ull b, ull c) {
    ull d; asm("fma.rn.f32x2 %0, %1, %2, %3;" : "=l"(d) : "l"(a), "l"(b), "l"(c)); return d;
}

// ---------------- K0: zero small accumulators ----------------
__global__ void zero_small() {
    int i = blockIdx.x * blockDim.x + threadIdx.x;
    if (i < B * HEADS * HC * HC) g_G[i] = 0.f;
    if (i < B * C) { g_qn[i] = 0.f; g_kn[i] = 0.f; }
}

// ================= K1: qkv = qkv_w @ x + qkv_b, X read ONCE =================
// grid (512, 1, 4), block (16,16). Dynamic smem: Xs[96][128] + As[96][49] = 68KB.
// Loops the 3 output m-blocks with X resident.
__global__ __launch_bounds__(256) void gemm_qkv_all(
    const float* __restrict__ qkv_w, const float* __restrict__ qkv_b,
    const float* __restrict__ x)
{
    extern __shared__ float sm[];
    float* Xs = sm;              // [96][128]
    float* As = sm + 96 * 128;   // [96][49]

    const int b = blockIdx.z;
    const long n0 = (long)blockIdx.x * 128;
    const int tx = threadIdx.x, ty = threadIdx.y;
    const int tid = ty * 16 + tx;
    const float* Xb = x + (long)b * C * HWPIX;
    float* Yb = g_qkv + (long)b * C3 * HWPIX;

    // load full X tile once: 96 x 128 = 3072 float4
#pragma unroll
    for (int e = 0; e < 12; e++) {
        int i4 = e * 256 + tid;
        int kk = i4 >> 5, j = (i4 & 31) * 4;
        *(float4*)&Xs[kk * 128 + j] = *(const float4*)&Xb[(long)kk * HWPIX + n0 + j];
    }

    for (int mb = 0; mb < 3; mb++) {
        ull acc[6][4];
#pragma unroll
        for (int i = 0; i < 6; i++)
#pragma unroll
            for (int j = 0; j < 4; j++) acc[i][j] = pk2(0.f);

        for (int kc = 0; kc < 96; kc += 48) {
            __syncthreads();
            // load A chunk: 96 x 48 = 4608 = 18*256
#pragma unroll
            for (int e = 0; e < 18; e++) {
                int idx = e * 256 + tid;
                int r = idx / 48, kk = idx % 48;
                As[r * 49 + kk] = qkv_w[(long)(mb * 96 + r) * 96 + kc + kk];
            }
            __syncthreads();
#pragma unroll
            for (int kk = 0; kk < 48; kk++) {
                ull a2[6];
#pragma unroll
                for (int i = 0; i < 6; i++) a2[i] = pk2(As[(ty * 6 + i) * 49 + kk]);
                const ull* xp = (const ull*)&Xs[(kc + kk) * 128 + tx * 8];
                ull x2[4] = { xp[0], xp[1], xp[2], xp[3] };
#pragma unroll
                for (int i = 0; i < 6; i++)
#pragma unroll
                    for (int j = 0; j < 4; j++) acc[i][j] = fma2(a2[i], x2[j], acc[i][j]);
            }
        }
        // epilogue for this m-block
#pragma unroll
        for (int i = 0; i < 6; i++) {
            int row = mb * 96 + ty * 6 + i;
            float bv = qkv_b[row];
            float2 p0 = unpk2(acc[i][0]), p1 = unpk2(acc[i][1]);
            float2 p2 = unpk2(acc[i][2]), p3 = unpk2(acc[i][3]);
            float* yp = Yb + (long)row * HWPIX + n0 + tx * 8;
            float4 v0 = { p0.x + bv, p0.y + bv, p1.x + bv, p1.y + bv };
            float4 v1 = { p2.x + bv, p2.y + bv, p3.x + bv, p3.y + bv };
            *(float4*)yp = v0;
            *(float4*)(yp + 4) = v1;
        }
    }
}

// ================= K2: FUSED dwconv(q,k) + norms + Gram =================
// grid (128 bands, 3 heads, 4 b), block 256. Band = 2 rows = 512 px.
// Dynamic smem: qk[512][68] (q at cols 0..31, k at 32..63) + weights 640 floats.
#define SQK 68
__global__ __launch_bounds__(256) void dwgram(
    const float* __restrict__ dw_w, const float* __restrict__ dw_b)
{
    extern __shared__ float sm[];
    float* qk  = sm;                 // [512][SQK]
    float* wsm = sm + 512 * SQK;     // [64][10]: w0..w8, bias

    const int col   = threadIdx.x;          // 0..255
    const int chunk = blockIdx.x;
    const int h     = blockIdx.y;
    const int b     = blockIdx.z;
    const int y0    = chunk * 2;
    const int lane  = col & 31;

    // stage weights+bias for the 64 channels of this head
    for (int i = col; i < 640; i += 256) {
        int lch = i / 10, j = i % 10;
        int ch = (lch < 32) ? (h * HC + lch) : (96 + h * HC + (lch - 32));
        wsm[i] = (j < 9) ? dw_w[ch * 9 + j] : dw_b[ch];
    }
    __syncthreads();

    // ---- phase A: depthwise conv for 64 channels (16 channel-quads) ----
    for (int quad = 0; quad < 16; quad++) {
        const int c4 = quad * 4;
        const int chg = (c4 < 32) ? (h * HC + c4) : (96 + h * HC + (c4 - 32));
        const float* P = g_qkv + ((long)(b * C3 + chg)) * HWPIX;

        float li[4][4], mi[4][4], ri[4][4];
#pragma unroll
        for (int rr = 0; rr < 4; rr++) {
            int y = y0 - 1 + rr;
            bool iny = ((unsigned)y < 256u);
#pragma unroll
            for (int cc = 0; cc < 4; cc++) {
                const float* row = P + (long)cc * HWPIX + y * WW;
                mi[rr][cc] = iny ? row[col] : 0.f;
                li[rr][cc] = (iny && col > 0)   ? row[col - 1] : 0.f;
                ri[rr][cc] = (iny && col < 255) ? row[col + 1] : 0.f;
            }
        }

        float v0[4], v1[4], ss[4];
#pragma unroll
        for (int cc = 0; cc < 4; cc++) {
            const float* w = &wsm[(c4 + cc) * 10];
            float w0 = w[0], w1 = w[1], w2 = w[2], w3 = w[3], w4 = w[4];
            float w5 = w[5], w6 = w[6], w7 = w[7], w8 = w[8], bias = w[9];
            float a = bias
                + w0 * li[0][cc] + w1 * mi[0][cc] + w2 * ri[0][cc]
                + w3 * li[1][cc] + w4 * mi[1][cc] + w5 * ri[1][cc]
                + w6 * li[2][cc] + w7 * mi[2][cc] + w8 * ri[2][cc];
            float bb = bias
                + w0 * li[1][cc] + w1 * mi[1][cc] + w2 * ri[1][cc]
                + w3 * li[2][cc] + w4 * mi[2][cc] + w5 * ri[2][cc]
                + w6 * li[3][cc] + w7 * mi[3][cc] + w8 * ri[3][cc];
            v0[cc] = a; v1[cc] = bb;
            ss[cc] = a * a + bb * bb;
        }
        // conflict-free STS.128: bank = (4p + c4) % 32, lane-consecutive p
        float4 f0 = { v0[0], v0[1], v0[2], v0[3] };
        float4 f1 = { v1[0], v1[1], v1[2], v1[3] };
        *(float4*)&qk[(long)col * SQK + c4] = f0;
        *(float4*)&qk[(long)(256 + col) * SQK + c4] = f1;

        // per-channel sum-of-squares -> g_qn / g_kn
#pragma unroll
        for (int cc = 0; cc < 4; cc++) {
            float s = ss[cc];
#pragma unroll
            for (int o = 16; o; o >>= 1) s += __shfl_down_sync(0xffffffffu, s, o);
            if (lane == 0) {
                int gc = (c4 < 32) ? (c4 + cc) : (c4 - 32 + cc);
                float* dst = (c4 < 32) ? &g_qn[b * C + h * HC + gc]
                                       : &g_kn[b * C + h * HC + gc];
                atomicAdd(dst, s);
            }
        }
    }
    __syncthreads();

    // ---- phase B: Gram over the 512 px, 4x4 thread tiles, f32x2 pairs ----
    const int sl  = col >> 6;              // p-slice 0..3
    const int cmb = col & 63;
    const int c0 = (cmb >> 3) << 2;        // 0,4,..,28
    const int d0 = (cmb & 7) << 2;         // 0,4,..,28
    ull acc[4][4];
#pragma unroll
    for (int i = 0; i < 4; i++)
#pragma unroll
        for (int j = 0; j < 4; j++) acc[i][j] = pk2(0.f);

    const int pbase = sl * 128;
#pragma unroll 4
    for (int it = 0; it < 64; it++) {
        const float* r0 = &qk[(long)(pbase + it * 2) * SQK];
        const float* r1 = r0 + SQK;
        float4 qa = *(const float4*)(r0 + c0);
        float4 qb = *(const float4*)(r1 + c0);
        float4 ka = *(const float4*)(r0 + 32 + d0);
        float4 kb = *(const float4*)(r1 + 32 + d0);
        ull q2[4] = { pack2(qa.x, qb.x), pack2(qa.y, qb.y),
                      pack2(qa.z, qb.z), pack2(qa.w, qb.w) };
        ull k2[4] = { pack2(ka.x, kb.x), pack2(ka.y, kb.y),
                      pack2(ka.z, kb.z), pack2(ka.w, kb.w) };
#pragma unroll
        for (int i = 0; i < 4; i++)
#pragma unroll
            for (int j = 0; j < 4; j++) acc[i][j] = fma2(q2[i], k2[j], acc[i][j]);
    }
    float* Gp = g_G + (long)(b * HEADS + h) * HC * HC;
#pragma unroll
    for (int i = 0; i < 4; i++)
#pragma unroll
        for (int j = 0; j < 4; j++) {
            float2 t = unpk2(acc[i][j]);
            atomicAdd(&Gp[(c0 + i) * HC + d0 + j], t.x + t.y);
        }
}

// ================= K2b: depthwise conv for v channels only =================
// grid (32 bands, 96 ch, 4 b), block 256 (thread = column), 8 rows per band.
__global__ __launch_bounds__(256) void dwconv_v(
    const float* __restrict__ dw_w, const float* __restrict__ dw_b)
{
    const int col  = threadIdx.x;
    const int band = blockIdx.x;
    const int vch  = blockIdx.y;           // 0..95
    const int b    = blockIdx.z;
    const int ch   = 192 + vch;            // global qkv channel
    const float* P = g_qkv + ((long)(b * C3 + ch)) * HWPIX;
    float*       O = g_v   + ((long)(b * C  + vch)) * HWPIX;

    float w[9];
#pragma unroll
    for (int t = 0; t < 9; t++) w[t] = __ldg(&dw_w[ch * 9 + t]);
    const float bias = __ldg(&dw_b[ch]);

    const int y0 = band * 8;
    float am1, a0, ap1, bm1, b0c, bp1;

    auto loadrow = [&](int y, float& l, float& m, float& r) {
        if (y < 0 || y > 255) { l = m = r = 0.f; }
        else {
            const float* row = P + y * WW;
            m = row[col];
            l = (col > 0)   ? row[col - 1] : 0.f;
            r = (col < 255) ? row[col + 1] : 0.f;
        }
    };
    loadrow(y0 - 1, am1, a0, ap1);
    loadrow(y0,     bm1, b0c, bp1);

#pragma unroll
    for (int dy = 0; dy < 8; dy++) {
        float cm1, c0v, cp1;
        loadrow(y0 + dy + 1, cm1, c0v, cp1);
        float v = bias
            + w[0] * am1 + w[1] * a0  + w[2] * ap1
            + w[3] * bm1 + w[4] * b0c + w[5] * bp1
            + w[6] * cm1 + w[7] * c0v + w[8] * cp1;
        O[(y0 + dy) * WW + col] = v;
        am1 = bm1; a0 = b0c; ap1 = bp1;
        bm1 = cm1; b0c = c0v; bp1 = cp1;
    }
}

// ================= K3: attn = softmax(G / (||q|| ||k||)) -> d_out tail ======
__global__ void attn_softmax(float* __restrict__ out)
{
    const int blk = blockIdx.x;            // b*3 + h
    const int b = blk / 3, h = blk % 3;
    const int c = threadIdx.x;
    float nq = fmaxf(sqrtf(g_qn[b * C + h * HC + c]), 1e-12f);

    float v[32];
#pragma unroll
    for (int d = 0; d < 32; d++) {
        float nk = fmaxf(sqrtf(g_kn[b * C + h * HC + d]), 1e-12f);
        v[d] = g_G[(blk * HC + c) * HC + d] / (nq * nk);
    }
    float m = -1e30f;
#pragma unroll
    for (int d = 0; d < 32; d++) m = fmaxf(m, v[d]);
    float s = 0.f;
#pragma unroll
    for (int d = 0; d < 32; d++) { v[d] = expf(v[d] - m); s += v[d]; }
    float inv = 1.f / s;
    float* ap = out + OUT_ELEMS + (long)blk * (HC * HC) + c * HC;
#pragma unroll
    for (int d = 0; d < 32; d++) ap[d] = v[d] * inv;
}

// ================= K4: M[b] = proj_w @ blockdiag(attn[b]) ===================
__global__ void make_M(const float* __restrict__ proj_w, const float* __restrict__ out)
{
    const int b = blockIdx.x, tid = threadIdx.x;
    const float* attn = out + OUT_ELEMS;
#pragma unroll 4
    for (int e = 0; e < 36; e++) {
        int idx = e * 256 + tid;            // 0..9215
        int o = idx / 96, g = idx % 96;
        int h = g >> 5, d = g & 31;
        const float* arow = attn + (long)(b * HEADS + h) * (HC * HC) + d;
        const float* prow = proj_w + o * 96 + h * HC;
        float s = 0.f;
#pragma unroll
        for (int cc = 0; cc < 32; cc++) s += prow[cc] * arow[cc * 32];
        g_M[(long)b * C * C + idx] = s;
    }
}

// ================= K5: out = M[b] @ v + proj_b (static-smem GEMM) ===========
__global__ __launch_bounds__(256) void gemm_out(
    const float* __restrict__ proj_b, float* __restrict__ out)
{
    __shared__ float As[96][49];
    __shared__ __align__(16) float Xs[48][128];

    const int b = blockIdx.z;
    const float* Ab = g_M + (long)b * C * C;
    const float* Xb = g_v + (long)b * C * HWPIX;
    float* Yb = out + (long)b * C * HWPIX;

    const long n0 = (long)blockIdx.x * 128;
    const int tx = threadIdx.x, ty = threadIdx.y;
    const int tid = ty * 16 + tx;

    ull acc[6][4];
#pragma unroll
    for (int i = 0; i < 6; i++)
#pragma unroll
        for (int j = 0; j < 4; j++) acc[i][j] = pk2(0.f);

    for (int kc = 0; kc < 96; kc += 48) {
#pragma unroll
        for (int e = 0; e < 18; e++) {
            int idx = e * 256 + tid;
            int r = idx / 48, kk = idx % 48;
            As[r][kk] = Ab[(long)r * 96 + kc + kk];
        }
#pragma unroll
        for (int e = 0; e < 6; e++) {
            int i4 = e * 256 + tid;
            int kk = i4 >> 5, j = (i4 & 31) * 4;
            *(float4*)&Xs[kk][j] = *(const float4*)&Xb[(long)(kc + kk) * HWPIX + n0 + j];
        }
        __syncthreads();
#pragma unroll
        for (int kk = 0; kk < 48; kk++) {
            ull a2[6];
#pragma unroll
            for (int i = 0; i < 6; i++) a2[i] = pk2(As[ty * 6 + i][kk]);
            const ull* xp = (const ull*)&Xs[kk][tx * 8];
            ull x2[4] = { xp[0], xp[1], xp[2], xp[3] };
#pragma unroll
            for (int i = 0; i < 6; i++)
#pragma unroll
                for (int j = 0; j < 4; j++) acc[i][j] = fma2(a2[i], x2[j], acc[i][j]);
        }
        __syncthreads();
    }
#pragma unroll
    for (int i = 0; i < 6; i++) {
        int row = ty * 6 + i;
        float bv = proj_b[row];
        float2 p0 = unpk2(acc[i][0]), p1 = unpk2(acc[i][1]);
        float2 p2 = unpk2(acc[i][2]), p3 = unpk2(acc[i][3]);
        float* yp = Yb + (long)row * HWPIX + n0 + tx * 8;
        float4 w0 = { p0.x + bv, p0.y + bv, p1.x + bv, p1.y + bv };
        float4 w1 = { p2.x + bv, p2.y + bv, p3.x + bv, p3.y + bv };
        *(float4*)yp = w0;
        *(float4*)(yp + 4) = w1;
    }
}

// ---------------- launch ----------------
extern "C" void kernel_launch(void* const* d_in, const int* in_sizes, int n_in,
                              void* d_out, int out_size)
{
    const float* x      = (const float*)d_in[0];
    const float* qkv_w  = (const float*)d_in[1];
    const float* qkv_b  = (const float*)d_in[2];
    const float* dw_w   = (const float*)d_in[3];
    const float* dw_b   = (const float*)d_in[4];
    const float* proj_w = (const float*)d_in[5];
    const float* proj_b = (const float*)d_in[6];
    float* out = (float*)d_out;

    const int smem_qkv = (96 * 128 + 96 * 49) * 4;            // 67,968 B
    const int smem_dwg = (512 * SQK + 640) * 4;               // 141,824 B
    cudaFuncSetAttribute(gemm_qkv_all, cudaFuncAttributeMaxDynamicSharedMemorySize, smem_qkv);
    cudaFuncSetAttribute(dwgram,       cudaFuncAttributeMaxDynamicSharedMemorySize, smem_dwg);

    zero_small<<<48, 256>>>();
    gemm_qkv_all<<<dim3(512, 1, B), dim3(16, 16), smem_qkv>>>(qkv_w, qkv_b, x);
    dwgram<<<dim3(128, HEADS, B), 256, smem_dwg>>>(dw_w, dw_b);
    dwconv_v<<<dim3(32, 96, B), 256>>>(dw_w, dw_b);
    attn_softmax<<<12, 32>>>(out);
    make_M<<<B, 256>>>(proj_w, out);
    gemm_out<<<dim3(512, 1, B), dim3(16, 16)>>>(proj_b, out);
}

// round 5
// speedup vs baseline: 1.5133x; 1.5133x over previous
#include <cuda_runtime.h>
#include <cuda_bf16.h>
#include <cstdint>

// Problem constants
#define B    4
#define C    96
#define C3   288
#define HH   256
#define WW   256
#define HWPIX 65536
#define HEADS 3
#define HC   32
#define OUT_ELEMS (B * C * HWPIX)

// ---------------- scratch (device globals) ----------------
__device__ float g_qkv[(size_t)B * C3 * HWPIX];  // post 1x1 conv
__device__ float g_dw [(size_t)B * C3 * HWPIX];  // post depthwise (q,k,v)
__device__ float g_G  [B * HEADS * HC * HC];
__device__ float g_qn [B * C];
__device__ float g_kn [B * C];
__device__ float g_M  [B * C * C];

// ---------------- helpers ----------------
__device__ __forceinline__ uint32_t packbf(float lo, float hi) {
    // low 16 bits = bf16(lo), high = bf16(hi)
    uint32_t r;
    asm("cvt.rn.bf16x2.f32 %0, %1, %2;" : "=r"(r) : "f"(hi), "f"(lo));
    return r;
}
__device__ __forceinline__ uint16_t bf16bits(float v) {
    __nv_bfloat16 h = __float2bfloat16(v);
    __nv_bfloat16_raw raw = h;      // public conversion to raw (has .x)
    return raw.x;
}
__device__ __forceinline__ float bf16val(float v) {
    return __bfloat162float(__float2bfloat16(v));
}

__device__ __forceinline__ void mma16816(float c[4], const uint32_t a[4],
                                         const uint32_t b[2]) {
    asm volatile(
        "mma.sync.aligned.m16n8k16.row.col.f32.bf16.bf16.f32 "
        "{%0,%1,%2,%3}, {%4,%5,%6,%7}, {%8,%9}, {%0,%1,%2,%3};"
        : "+f"(c[0]), "+f"(c[1]), "+f"(c[2]), "+f"(c[3])
        : "r"(a[0]), "r"(a[1]), "r"(a[2]), "r"(a[3]), "r"(b[0]), "r"(b[1]));
}

// ================= tensor-core GEMM via mma.sync (bf16 hi/lo 3-product) ====
// Computes O[ch][px] = sum_k W[ch][k] X[k][px] + bias[ch] for NG groups of 96 ch.
// Block: 256 thr (8 warps), tile = NG*96 ch x 128 px. Warp: 96 ch x 16 px.
// Smem: B-tile transposed [128 px][104 k] bf16 hi+lo; A-tile [96][104] hi+lo.
#define KP 104  // bf16 pitch (52 words -> conflict-free frag loads)

template<int NG>
__global__ __launch_bounds__(256) void tmma_gemm(
    const float* __restrict__ Xin, const float* __restrict__ Win,
    const float* __restrict__ bias, float* __restrict__ Oout)
{
    extern __shared__ __align__(16) uint16_t sm[];
    uint16_t* sbh = sm;                       // B hi [128][KP]
    uint16_t* sbl = sm + 128 * KP;            // B lo
    uint16_t* sah = sm + 2 * 128 * KP;        // A hi [96][KP]
    uint16_t* sal = sm + 2 * 128 * KP + 96 * KP;

    const int tid  = threadIdx.x;
    const int warp = tid >> 5;
    const int l    = tid & 31;
    const int b    = blockIdx.z;
    const long n0  = (long)blockIdx.x * 128;

    const float* Xb; const float* Wb; float* Ob;
    if constexpr (NG == 3) {
        Xb = Xin + (long)b * C * HWPIX;
        Wb = Win;
        Ob = g_qkv + (long)b * C3 * HWPIX;
    } else {
        Xb = g_dw + ((long)b * C3 + 192) * HWPIX;   // v channels
        Wb = g_M + (long)b * C * C;
        Ob = Oout + (long)b * C * HWPIX;
    }

    // ---- B tile: X[k][px] -> smem [px][k] bf16 hi/lo ----
    {
        const int px = tid & 127;
        const int kh = tid >> 7;
        for (int k2 = kh; k2 < 48; k2 += 2) {
            const int k = k2 * 2;
            float v0 = Xb[(long)k * HWPIX + n0 + px];
            float v1 = Xb[(long)(k + 1) * HWPIX + n0 + px];
            float h0 = bf16val(v0);
            float h1 = bf16val(v1);
            *(uint32_t*)&sbh[px * KP + k] = packbf(v0, v1);
            *(uint32_t*)&sbl[px * KP + k] = packbf(v0 - h0, v1 - h1);
        }
    }

    const int wpx = warp * 16;      // warp's pixel base within tile
    const int lr = l >> 2;          // 0..7
    const int lc = (l & 3) * 2;     // 0,2,4,6

    for (int g = 0; g < NG; g++) {
        __syncthreads();            // protect A smem reuse
        // ---- A tile: W[g][m][k] -> smem hi/lo ----
        const float* Wg = Wb + (long)g * 96 * 96;
        for (int i = tid; i < 96 * 96; i += 256) {
            int m = i / 96, k = i - m * 96;
            float w = Wg[i];
            sah[m * KP + k] = bf16bits(w);
            sal[m * KP + k] = bf16bits(w - bf16val(w));
        }
        __syncthreads();

        float c[6][2][4];
#pragma unroll
        for (int mt = 0; mt < 6; mt++)
#pragma unroll
            for (int nt = 0; nt < 2; nt++)
#pragma unroll
                for (int j = 0; j < 4; j++) c[mt][nt][j] = 0.f;

#pragma unroll
        for (int s = 0; s < 6; s++) {
            const int k0 = s * 16;
            uint32_t bh[2][2], bl[2][2];
#pragma unroll
            for (int nt = 0; nt < 2; nt++) {
                const int n = wpx + nt * 8 + lr;
                bh[nt][0] = *(const uint32_t*)&sbh[n * KP + k0 + lc];
                bh[nt][1] = *(const uint32_t*)&sbh[n * KP + k0 + lc + 8];
                bl[nt][0] = *(const uint32_t*)&sbl[n * KP + k0 + lc];
                bl[nt][1] = *(const uint32_t*)&sbl[n * KP + k0 + lc + 8];
            }
#pragma unroll
            for (int mt = 0; mt < 6; mt++) {
                const int r = mt * 16 + lr;
                uint32_t ah[4], al[4];
                ah[0] = *(const uint32_t*)&sah[r * KP + k0 + lc];
                ah[1] = *(const uint32_t*)&sah[(r + 8) * KP + k0 + lc];
                ah[2] = *(const uint32_t*)&sah[r * KP + k0 + lc + 8];
                ah[3] = *(const uint32_t*)&sah[(r + 8) * KP + k0 + lc + 8];
                al[0] = *(const uint32_t*)&sal[r * KP + k0 + lc];
                al[1] = *(const uint32_t*)&sal[(r + 8) * KP + k0 + lc];
                al[2] = *(const uint32_t*)&sal[r * KP + k0 + lc + 8];
                al[3] = *(const uint32_t*)&sal[(r + 8) * KP + k0 + lc + 8];
#pragma unroll
                for (int nt = 0; nt < 2; nt++) {
                    mma16816(c[mt][nt], ah, bh[nt]);
                    mma16816(c[mt][nt], ah, bl[nt]);
                    mma16816(c[mt][nt], al, bh[nt]);
                }
            }
        }

        // ---- epilogue: bias + store ----
#pragma unroll
        for (int mt = 0; mt < 6; mt++) {
#pragma unroll
            for (int nt = 0; nt < 2; nt++) {
                const int ch0 = g * 96 + mt * 16 + lr;
                const long px = n0 + wpx + nt * 8 + lc;
                float b0 = __ldg(&bias[ch0]);
                float b1 = __ldg(&bias[ch0 + 8]);
                float2 v0 = { c[mt][nt][0] + b0, c[mt][nt][1] + b0 };
                float2 v1 = { c[mt][nt][2] + b1, c[mt][nt][3] + b1 };
                *(float2*)&Ob[(long)ch0 * HWPIX + px] = v0;
                *(float2*)&Ob[(long)(ch0 + 8) * HWPIX + px] = v1;
            }
        }
    }
}

// ---------------- K0: zero small accumulators ----------------
__global__ void zero_small() {
    int i = blockIdx.x * blockDim.x + threadIdx.x;
    if (i < B * HEADS * HC * HC) g_G[i] = 0.f;
    if (i < B * C) { g_qn[i] = 0.f; g_kn[i] = 0.f; }
}

// ---------------- K2: 3x3 depthwise conv + q/k sum-of-squares ----------
__global__ __launch_bounds__(256) void dwconv(
    const float* __restrict__ dw_w, const float* __restrict__ dw_b)
{
    const int col  = threadIdx.x;
    const int band = blockIdx.x;
    const int ch   = blockIdx.y;
    const int b    = blockIdx.z;
    const float* P = g_qkv + ((long)(b * C3 + ch)) * HWPIX;
    float*       O = g_dw  + ((long)(b * C3 + ch)) * HWPIX;

    float w[9];
#pragma unroll
    for (int t = 0; t < 9; t++) w[t] = __ldg(&dw_w[ch * 9 + t]);
    const float bias = __ldg(&dw_b[ch]);

    const int y0 = band * 8;
    float am1, a0, ap1, bm1, b0c, bp1;

    auto loadrow = [&](int y, float& lft, float& m, float& r) {
        if (y < 0 || y > 255) { lft = m = r = 0.f; }
        else {
            const float* row = P + y * WW;
            m = row[col];
            lft = (col > 0)   ? row[col - 1] : 0.f;
            r = (col < 255) ? row[col + 1] : 0.f;
        }
    };
    loadrow(y0 - 1, am1, a0, ap1);
    loadrow(y0,     bm1, b0c, bp1);

    float ss = 0.f;
#pragma unroll
    for (int dy = 0; dy < 8; dy++) {
        float cm1, c0v, cp1;
        loadrow(y0 + dy + 1, cm1, c0v, cp1);
        float v = bias
            + w[0] * am1 + w[1] * a0  + w[2] * ap1
            + w[3] * bm1 + w[4] * b0c + w[5] * bp1
            + w[6] * cm1 + w[7] * c0v + w[8] * cp1;
        O[(y0 + dy) * WW + col] = v;
        if (ch < 192) ss += v * v;
        am1 = bm1; a0 = b0c; ap1 = bp1;
        bm1 = cm1; b0c = c0v; bp1 = cp1;
    }

    if (ch < 192) {
#pragma unroll
        for (int o = 16; o; o >>= 1) ss += __shfl_down_sync(0xffffffffu, ss, o);
        __shared__ float red[8];
        if ((threadIdx.x & 31) == 0) red[threadIdx.x >> 5] = ss;
        __syncthreads();
        if (threadIdx.x == 0) {
            float t = 0.f;
#pragma unroll
            for (int i = 0; i < 8; i++) t += red[i];
            float* dst = (ch < 96) ? &g_qn[b * C + ch] : &g_kn[b * C + ch - 96];
            atomicAdd(dst, t);
        }
    }
}

// ---------------- K3: Gram ----------------
__global__ __launch_bounds__(256) void gram()
{
    __shared__ float q_s[32 * 132];
    __shared__ __align__(16) float k_s[128 * 36];

    const int chunk = blockIdx.x, h = blockIdx.y, b = blockIdx.z;
    const float* q = g_dw + ((long)(b * C3 + h * HC)) * HWPIX;
    const float* k = g_dw + ((long)(b * C3 + 96 + h * HC)) * HWPIX;
    const int tid = threadIdx.x;
    const int c  = tid >> 3;
    const int d0 = (tid & 7) * 4;

    float acc0 = 0.f, acc1 = 0.f, acc2 = 0.f, acc3 = 0.f;
    const long base = (long)chunk * 2048;

    for (int s = 0; s < 16; s++) {
        const long n = base + s * 128;
        __syncthreads();
#pragma unroll
        for (int e = 0; e < 16; e++) {
            int idx = e * 256 + tid;
            int cc = idx >> 7, p = idx & 127;
            q_s[cc * 132 + p] = q[(long)cc * HWPIX + n + p];
            k_s[p * 36 + cc]  = k[(long)cc * HWPIX + n + p];
        }
        __syncthreads();
#pragma unroll 8
        for (int p = 0; p < 128; p++) {
            float qv = q_s[c * 132 + p];
            float4 kv = *(const float4*)&k_s[p * 36 + d0];
            acc0 += qv * kv.x; acc1 += qv * kv.y;
            acc2 += qv * kv.z; acc3 += qv * kv.w;
        }
    }
    float* Gp = g_G + ((long)((b * HEADS + h) * HC + c)) * HC + d0;
    atomicAdd(Gp + 0, acc0);
    atomicAdd(Gp + 1, acc1);
    atomicAdd(Gp + 2, acc2);
    atomicAdd(Gp + 3, acc3);
}

// ---------------- K3b: softmax(G / (||q|| ||k||)) -> d_out tail ------------
__global__ void attn_softmax(float* __restrict__ out)
{
    const int blk = blockIdx.x;
    const int b = blk / 3, h = blk % 3;
    const int c = threadIdx.x;
    float nq = fmaxf(sqrtf(g_qn[b * C + h * HC + c]), 1e-12f);

    float v[32];
#pragma unroll
    for (int d = 0; d < 32; d++) {
        float nk = fmaxf(sqrtf(g_kn[b * C + h * HC + d]), 1e-12f);
        v[d] = g_G[(blk * HC + c) * HC + d] / (nq * nk);
    }
    float m = -1e30f;
#pragma unroll
    for (int d = 0; d < 32; d++) m = fmaxf(m, v[d]);
    float s = 0.f;
#pragma unroll
    for (int d = 0; d < 32; d++) { v[d] = expf(v[d] - m); s += v[d]; }
    float inv = 1.f / s;
    float* ap = out + OUT_ELEMS + (long)blk * (HC * HC) + c * HC;
#pragma unroll
    for (int d = 0; d < 32; d++) ap[d] = v[d] * inv;
}

// ---------------- K3c: M[b] = proj_w @ blockdiag(attn[b]) ----------------
__global__ void make_M(const float* __restrict__ proj_w, const float* __restrict__ out)
{
    const int b = blockIdx.x, tid = threadIdx.x;
    const float* attn = out + OUT_ELEMS;
#pragma unroll 4
    for (int e = 0; e < 36; e++) {
        int idx = e * 256 + tid;
        int o = idx / 96, g = idx % 96;
        int h = g >> 5, d = g & 31;
        const float* arow = attn + (long)(b * HEADS + h) * (HC * HC) + d;
        const float* prow = proj_w + o * 96 + h * HC;
        float s = 0.f;
#pragma unroll
        for (int cc = 0; cc < 32; cc++) s += prow[cc] * arow[cc * 32];
        g_M[(long)b * C * C + idx] = s;
    }
}

// ---------------- launch ----------------
extern "C" void kernel_launch(void* const* d_in, const int* in_sizes, int n_in,
                              void* d_out, int out_size)
{
    const float* x      = (const float*)d_in[0];
    const float* qkv_w  = (const float*)d_in[1];
    const float* qkv_b  = (const float*)d_in[2];
    const float* dw_w   = (const float*)d_in[3];
    const float* dw_b   = (const float*)d_in[4];
    const float* proj_w = (const float*)d_in[5];
    const float* proj_b = (const float*)d_in[6];
    float* out = (float*)d_out;

    const int smem_bytes = (2 * 128 * KP + 2 * 96 * KP) * 2;  // 93,184 B
    cudaFuncSetAttribute(tmma_gemm<3>, cudaFuncAttributeMaxDynamicSharedMemorySize, smem_bytes);
    cudaFuncSetAttribute(tmma_gemm<1>, cudaFuncAttributeMaxDynamicSharedMemorySize, smem_bytes);

    zero_small<<<48, 256>>>();
    tmma_gemm<3><<<dim3(512, 1, B), 256, smem_bytes>>>(x, qkv_w, qkv_b, nullptr);
    dwconv<<<dim3(32, C3, B), 256>>>(dw_w, dw_b);
    gram<<<dim3(32, HEADS, B), 256>>>();
    attn_softmax<<<12, 32>>>(out);
    make_M<<<B, 256>>>(proj_w, out);
    tmma_gemm<1><<<dim3(512, 1, B), 256, smem_bytes>>>(nullptr, nullptr, proj_b, out);
}

// round 6
// speedup vs baseline: 1.7797x; 1.1760x over previous
#include <cuda_runtime.h>
#include <cuda_bf16.h>
#include <cstdint>

// Problem constants
#define B    4
#define C    96
#define C3   288
#define HH   256
#define WW   256
#define HWPIX 65536
#define HEADS 3
#define HC   32
#define OUT_ELEMS (B * C * HWPIX)

// ---------------- scratch (device globals) ----------------
__device__ float g_qkv[(size_t)B * C3 * HWPIX];  // post 1x1 conv
__device__ float g_dw [(size_t)B * C3 * HWPIX];  // post depthwise; q,k packed bf16 hi/lo, v fp32
__device__ float g_G  [B * HEADS * HC * HC];
__device__ float g_qn [B * C];
__device__ float g_kn [B * C];
__device__ float g_M  [B * C * C];

// ---------------- helpers ----------------
__device__ __forceinline__ uint32_t packbf(float lo, float hi) {
    // low 16 bits = bf16(lo), high 16 = bf16(hi)
    uint32_t r;
    asm("cvt.rn.bf16x2.f32 %0, %1, %2;" : "=r"(r) : "f"(hi), "f"(lo));
    return r;
}
__device__ __forceinline__ uint16_t bf16bits(float v) {
    __nv_bfloat16 h = __float2bfloat16(v);
    __nv_bfloat16_raw raw = h;
    return raw.x;
}
__device__ __forceinline__ float bf16val(float v) {
    return __bfloat162float(__float2bfloat16(v));
}
__device__ __forceinline__ uint32_t prmt0(uint32_t a, uint32_t sel) {
    uint32_t d, z = 0;
    asm("prmt.b32 %0, %1, %2, %3;" : "=r"(d) : "r"(a), "r"(z), "r"(sel));
    return d;
}

__device__ __forceinline__ void mma16816(float c[4], const uint32_t a[4],
                                         const uint32_t b[2]) {
    asm volatile(
        "mma.sync.aligned.m16n8k16.row.col.f32.bf16.bf16.f32 "
        "{%0,%1,%2,%3}, {%4,%5,%6,%7}, {%8,%9}, {%0,%1,%2,%3};"
        : "+f"(c[0]), "+f"(c[1]), "+f"(c[2]), "+f"(c[3])
        : "r"(a[0]), "r"(a[1]), "r"(a[2]), "r"(a[3]), "r"(b[0]), "r"(b[1]));
}

// ================= tensor-core GEMM via mma.sync (bf16 hi/lo 3-product) ====
#define KP 104  // bf16 pitch

template<int NG>
__global__ __launch_bounds__(256) void tmma_gemm(
    const float* __restrict__ Xin, const float* __restrict__ Win,
    const float* __restrict__ bias, float* __restrict__ Oout)
{
    extern __shared__ __align__(16) uint16_t sm[];
    uint16_t* sbh = sm;                       // B hi [128][KP]
    uint16_t* sbl = sm + 128 * KP;            // B lo
    uint16_t* sah = sm + 2 * 128 * KP;        // A hi [96][KP]
    uint16_t* sal = sm + 2 * 128 * KP + 96 * KP;

    const int tid  = threadIdx.x;
    const int warp = tid >> 5;
    const int l    = tid & 31;
    const int b    = blockIdx.z;
    const long n0  = (long)blockIdx.x * 128;

    const float* Xb; const float* Wb; float* Ob;
    if constexpr (NG == 3) {
        Xb = Xin + (long)b * C * HWPIX;
        Wb = Win;
        Ob = g_qkv + (long)b * C3 * HWPIX;
    } else {
        Xb = g_dw + ((long)b * C3 + 192) * HWPIX;   // v channels (fp32)
        Wb = g_M + (long)b * C * C;
        Ob = Oout + (long)b * C * HWPIX;
    }

    // ---- B tile: X[k][px] -> smem [px][k] bf16 hi/lo ----
    {
        const int px = tid & 127;
        const int kh = tid >> 7;
        for (int k2 = kh; k2 < 48; k2 += 2) {
            const int k = k2 * 2;
            float v0 = Xb[(long)k * HWPIX + n0 + px];
            float v1 = Xb[(long)(k + 1) * HWPIX + n0 + px];
            float h0 = bf16val(v0);
            float h1 = bf16val(v1);
            *(uint32_t*)&sbh[px * KP + k] = packbf(v0, v1);
            *(uint32_t*)&sbl[px * KP + k] = packbf(v0 - h0, v1 - h1);
        }
    }

    const int wpx = warp * 16;
    const int lr = l >> 2;
    const int lc = (l & 3) * 2;

    for (int g = 0; g < NG; g++) {
        __syncthreads();
        const float* Wg = Wb + (long)g * 96 * 96;
        for (int i = tid; i < 96 * 96; i += 256) {
            int m = i / 96, k = i - m * 96;
            float w = Wg[i];
            sah[m * KP + k] = bf16bits(w);
            sal[m * KP + k] = bf16bits(w - bf16val(w));
        }
        __syncthreads();

        float c[6][2][4];
#pragma unroll
        for (int mt = 0; mt < 6; mt++)
#pragma unroll
            for (int nt = 0; nt < 2; nt++)
#pragma unroll
                for (int j = 0; j < 4; j++) c[mt][nt][j] = 0.f;

#pragma unroll
        for (int s = 0; s < 6; s++) {
            const int k0 = s * 16;
            uint32_t bh[2][2], bl[2][2];
#pragma unroll
            for (int nt = 0; nt < 2; nt++) {
                const int n = wpx + nt * 8 + lr;
                bh[nt][0] = *(const uint32_t*)&sbh[n * KP + k0 + lc];
                bh[nt][1] = *(const uint32_t*)&sbh[n * KP + k0 + lc + 8];
                bl[nt][0] = *(const uint32_t*)&sbl[n * KP + k0 + lc];
                bl[nt][1] = *(const uint32_t*)&sbl[n * KP + k0 + lc + 8];
            }
#pragma unroll
            for (int mt = 0; mt < 6; mt++) {
                const int r = mt * 16 + lr;
                uint32_t ah[4], al[4];
                ah[0] = *(const uint32_t*)&sah[r * KP + k0 + lc];
                ah[1] = *(const uint32_t*)&sah[(r + 8) * KP + k0 + lc];
                ah[2] = *(const uint32_t*)&sah[r * KP + k0 + lc + 8];
                ah[3] = *(const uint32_t*)&sah[(r + 8) * KP + k0 + lc + 8];
                al[0] = *(const uint32_t*)&sal[r * KP + k0 + lc];
                al[1] = *(const uint32_t*)&sal[(r + 8) * KP + k0 + lc];
                al[2] = *(const uint32_t*)&sal[r * KP + k0 + lc + 8];
                al[3] = *(const uint32_t*)&sal[(r + 8) * KP + k0 + lc + 8];
#pragma unroll
                for (int nt = 0; nt < 2; nt++) {
                    mma16816(c[mt][nt], ah, bh[nt]);
                    mma16816(c[mt][nt], ah, bl[nt]);
                    mma16816(c[mt][nt], al, bh[nt]);
                }
            }
        }

#pragma unroll
        for (int mt = 0; mt < 6; mt++) {
#pragma unroll
            for (int nt = 0; nt < 2; nt++) {
                const int ch0 = g * 96 + mt * 16 + lr;
                const long px = n0 + wpx + nt * 8 + lc;
                float b0 = __ldg(&bias[ch0]);
                float b1 = __ldg(&bias[ch0 + 8]);
                float2 v0 = { c[mt][nt][0] + b0, c[mt][nt][1] + b0 };
                float2 v1 = { c[mt][nt][2] + b1, c[mt][nt][3] + b1 };
                *(float2*)&Ob[(long)ch0 * HWPIX + px] = v0;
                *(float2*)&Ob[(long)(ch0 + 8) * HWPIX + px] = v1;
            }
        }
    }
}

// ---------------- K0: zero small accumulators ----------------
__global__ void zero_small() {
    int i = blockIdx.x * blockDim.x + threadIdx.x;
    if (i < B * HEADS * HC * HC) g_G[i] = 0.f;
    if (i < B * C) { g_qn[i] = 0.f; g_kn[i] = 0.f; }
}

// ---------------- K2: 3x3 depthwise conv; q,k packed bf16 hi/lo + norms ----
__global__ __launch_bounds__(256) void dwconv(
    const float* __restrict__ dw_w, const float* __restrict__ dw_b)
{
    const int col  = threadIdx.x;
    const int band = blockIdx.x;
    const int ch   = blockIdx.y;
    const int b    = blockIdx.z;
    const float* P = g_qkv + ((long)(b * C3 + ch)) * HWPIX;
    float*       O = g_dw  + ((long)(b * C3 + ch)) * HWPIX;

    float w[9];
#pragma unroll
    for (int t = 0; t < 9; t++) w[t] = __ldg(&dw_w[ch * 9 + t]);
    const float bias = __ldg(&dw_b[ch]);

    const int y0 = band * 8;
    float am1, a0, ap1, bm1, b0c, bp1;

    auto loadrow = [&](int y, float& lft, float& m, float& r) {
        if (y < 0 || y > 255) { lft = m = r = 0.f; }
        else {
            const float* row = P + y * WW;
            m = row[col];
            lft = (col > 0)   ? row[col - 1] : 0.f;
            r = (col < 255) ? row[col + 1] : 0.f;
        }
    };
    loadrow(y0 - 1, am1, a0, ap1);
    loadrow(y0,     bm1, b0c, bp1);

    float ss = 0.f;
#pragma unroll
    for (int dy = 0; dy < 8; dy++) {
        float cm1, c0v, cp1;
        loadrow(y0 + dy + 1, cm1, c0v, cp1);
        float v = bias
            + w[0] * am1 + w[1] * a0  + w[2] * ap1
            + w[3] * bm1 + w[4] * b0c + w[5] * bp1
            + w[6] * cm1 + w[7] * c0v + w[8] * cp1;
        if (ch < 192) {
            ss += v * v;
            uint32_t packed = packbf(v, v - bf16val(v));  // lo16 = bf16(v), hi16 = residual
            ((uint32_t*)O)[(y0 + dy) * WW + col] = packed;
        } else {
            O[(y0 + dy) * WW + col] = v;
        }
        am1 = bm1; a0 = b0c; ap1 = bp1;
        bm1 = cm1; b0c = c0v; bp1 = cp1;
    }

    if (ch < 192) {
#pragma unroll
        for (int o = 16; o; o >>= 1) ss += __shfl_down_sync(0xffffffffu, ss, o);
        __shared__ float red[8];
        if ((threadIdx.x & 31) == 0) red[threadIdx.x >> 5] = ss;
        __syncthreads();
        if (threadIdx.x == 0) {
            float t = 0.f;
#pragma unroll
            for (int i = 0; i < 8; i++) t += red[i];
            float* dst = (ch < 96) ? &g_qn[b * C + ch] : &g_kn[b * C + ch - 96];
            atomicAdd(dst, t);
        }
    }
}

// ---------------- K3: Gram via mma.sync on packed {hi,lo} words -------------
// grid (32, 3, 4), block 256 (8 warps). Chunk = 2048 px, 8 slices of 256 px.
// smem: qs[32][260] + ks[32][260] uint32 (66,560 B, dynamic).
// a = {qh,ql} packed; b1 = prmt {kh,kh}; b2 = prmt {kl,0}:
//   a.b1 + a.b2 = qh kh + ql kh + qh kl  (3-product split, 2 MMAs, 0 cvt)
#define GPITCH 260
__global__ __launch_bounds__(256) void gram_mma()
{
    extern __shared__ uint32_t gsm[];
    uint32_t* qs = gsm;
    uint32_t* ks = gsm + 32 * GPITCH;
    float* red = (float*)gsm;          // reused after compute: [8][1024]

    const int chunk = blockIdx.x, h = blockIdx.y, b = blockIdx.z;
    const uint32_t* qg = (const uint32_t*)g_dw + ((long)(b * C3 + h * HC)) * HWPIX;
    const uint32_t* kg = (const uint32_t*)g_dw + ((long)(b * C3 + 96 + h * HC)) * HWPIX;
    const int tid = threadIdx.x, w = tid >> 5, l = tid & 31;
    const int lr = l >> 2, lq = l & 3;

    float c[2][4][4];
#pragma unroll
    for (int mt = 0; mt < 2; mt++)
#pragma unroll
        for (int nt = 0; nt < 4; nt++)
#pragma unroll
            for (int j = 0; j < 4; j++) c[mt][nt][j] = 0.f;

    const long base = (long)chunk * 2048;
    for (int s = 0; s < 8; s++) {
        const long n = base + s * 256;
        __syncthreads();
#pragma unroll
        for (int e = 0; e < 8; e++) {
            int i4 = e * 256 + tid;
            int ch = i4 >> 6, p4 = (i4 & 63) * 4;
            *(uint4*)&qs[ch * GPITCH + p4] = *(const uint4*)&qg[(long)ch * HWPIX + n + p4];
            *(uint4*)&ks[ch * GPITCH + p4] = *(const uint4*)&kg[(long)ch * HWPIX + n + p4];
        }
        __syncthreads();

        const int pxw = w * 32;
#pragma unroll
        for (int st = 0; st < 4; st++) {
            const int pxb = pxw + st * 8;
            uint32_t bh[4][2], bl[4][2];
#pragma unroll
            for (int nt = 0; nt < 4; nt++) {
                uint32_t r0 = ks[(nt * 8 + lr) * GPITCH + pxb + lq];
                uint32_t r1 = ks[(nt * 8 + lr) * GPITCH + pxb + 4 + lq];
                bh[nt][0] = prmt0(r0, 0x1010u); bl[nt][0] = prmt0(r0, 0x4432u);
                bh[nt][1] = prmt0(r1, 0x1010u); bl[nt][1] = prmt0(r1, 0x4432u);
            }
#pragma unroll
            for (int mt = 0; mt < 2; mt++) {
                uint32_t a[4];
                a[0] = qs[(mt * 16 + lr) * GPITCH + pxb + lq];
                a[1] = qs[(mt * 16 + 8 + lr) * GPITCH + pxb + lq];
                a[2] = qs[(mt * 16 + lr) * GPITCH + pxb + 4 + lq];
                a[3] = qs[(mt * 16 + 8 + lr) * GPITCH + pxb + 4 + lq];
#pragma unroll
                for (int nt = 0; nt < 4; nt++) {
                    mma16816(c[mt][nt], a, bh[nt]);
                    mma16816(c[mt][nt], a, bl[nt]);
                }
            }
        }
    }

    // warp partials -> smem -> block reduce -> atomics
    __syncthreads();
#pragma unroll
    for (int mt = 0; mt < 2; mt++)
#pragma unroll
        for (int nt = 0; nt < 4; nt++)
#pragma unroll
            for (int j = 0; j < 4; j++) {
                int row = mt * 16 + lr + ((j >> 1) << 3);
                int cl  = nt * 8 + lq * 2 + (j & 1);
                red[w * 1024 + row * 32 + cl] = c[mt][nt][j];
            }
    __syncthreads();
    float* Gp = g_G + (long)(b * HEADS + h) * HC * HC;
    for (int i = tid; i < 1024; i += 256) {
        float sum = 0.f;
#pragma unroll
        for (int ww = 0; ww < 8; ww++) sum += red[ww * 1024 + i];
        atomicAdd(&Gp[i], sum);
    }
}

// ---------------- K3b: softmax(G / (||q|| ||k||)) -> d_out tail ------------
__global__ void attn_softmax(float* __restrict__ out)
{
    const int blk = blockIdx.x;
    const int b = blk / 3, h = blk % 3;
    const int c = threadIdx.x;
    float nq = fmaxf(sqrtf(g_qn[b * C + h * HC + c]), 1e-12f);

    float v[32];
#pragma unroll
    for (int d = 0; d < 32; d++) {
        float nk = fmaxf(sqrtf(g_kn[b * C + h * HC + d]), 1e-12f);
        v[d] = g_G[(blk * HC + c) * HC + d] / (nq * nk);
    }
    float m = -1e30f;
#pragma unroll
    for (int d = 0; d < 32; d++) m = fmaxf(m, v[d]);
    float s = 0.f;
#pragma unroll
    for (int d = 0; d < 32; d++) { v[d] = expf(v[d] - m); s += v[d]; }
    float inv = 1.f / s;
    float* ap = out + OUT_ELEMS + (long)blk * (HC * HC) + c * HC;
#pragma unroll
    for (int d = 0; d < 32; d++) ap[d] = v[d] * inv;
}

// ---------------- K3c: M[b] = proj_w @ blockdiag(attn[b]) ----------------
__global__ void make_M(const float* __restrict__ proj_w, const float* __restrict__ out)
{
    const int b = blockIdx.x, tid = threadIdx.x;
    const float* attn = out + OUT_ELEMS;
#pragma unroll 4
    for (int e = 0; e < 36; e++) {
        int idx = e * 256 + tid;
        int o = idx / 96, g = idx % 96;
        int h = g >> 5, d = g & 31;
        const float* arow = attn + (long)(b * HEADS + h) * (HC * HC) + d;
        const float* prow = proj_w + o * 96 + h * HC;
        float s = 0.f;
#pragma unroll
        for (int cc = 0; cc < 32; cc++) s += prow[cc] * arow[cc * 32];
        g_M[(long)b * C * C + idx] = s;
    }
}

// ---------------- launch ----------------
extern "C" void kernel_launch(void* const* d_in, const int* in_sizes, int n_in,
                              void* d_out, int out_size)
{
    const float* x      = (const float*)d_in[0];
    const float* qkv_w  = (const float*)d_in[1];
    const float* qkv_b  = (const float*)d_in[2];
    const float* dw_w   = (const float*)d_in[3];
    const float* dw_b   = (const float*)d_in[4];
    const float* proj_w = (const float*)d_in[5];
    const float* proj_b = (const float*)d_in[6];
    float* out = (float*)d_out;

    const int smem_gemm = (2 * 128 * KP + 2 * 96 * KP) * 2;   // 93,184 B
    const int smem_gram = 2 * 32 * GPITCH * 4;                // 66,560 B
    cudaFuncSetAttribute(tmma_gemm<3>, cudaFuncAttributeMaxDynamicSharedMemorySize, smem_gemm);
    cudaFuncSetAttribute(tmma_gemm<1>, cudaFuncAttributeMaxDynamicSharedMemorySize, smem_gemm);
    cudaFuncSetAttribute(gram_mma,     cudaFuncAttributeMaxDynamicSharedMemorySize, smem_gram);

    zero_small<<<48, 256>>>();
    tmma_gemm<3><<<dim3(512, 1, B), 256, smem_gemm>>>(x, qkv_w, qkv_b, nullptr);
    dwconv<<<dim3(32, C3, B), 256>>>(dw_w, dw_b);
    gram_mma<<<dim3(32, HEADS, B), 256, smem_gram>>>();
    attn_softmax<<<12, 32>>>(out);
    make_M<<<B, 256>>>(proj_w, out);
    tmma_gemm<1><<<dim3(512, 1, B), 256, smem_gemm>>>(nullptr, nullptr, proj_b, out);
}

// round 7
// speedup vs baseline: 2.0083x; 1.1285x over previous
#include <cuda_runtime.h>
#include <cuda_bf16.h>
#include <cstdint>

// Problem constants
#define B    4
#define C    96
#define C3   288
#define HH   256
#define WW   256
#define HWPIX 65536
#define HEADS 3
#define HC   32
#define OUT_ELEMS (B * C * HWPIX)

// ---------------- scratch (device globals) ----------------
__device__ float g_qkv[(size_t)B * C3 * HWPIX];  // post 1x1 conv (fp32)
__device__ float g_dw [(size_t)B * C3 * HWPIX];  // post dw; ALL channels packed {bf16 hi, bf16 lo} uint32
__device__ float g_G  [B * HEADS * HC * HC];
__device__ float g_qn [B * C];
__device__ float g_kn [B * C];
__device__ float g_M  [B * C * C];

// ---------------- helpers ----------------
__device__ __forceinline__ uint32_t packbf(float lo, float hi) {
    // low 16 bits = bf16(lo), high 16 = bf16(hi)
    uint32_t r;
    asm("cvt.rn.bf16x2.f32 %0, %1, %2;" : "=r"(r) : "f"(hi), "f"(lo));
    return r;
}
__device__ __forceinline__ uint16_t bf16bits(float v) {
    __nv_bfloat16 h = __float2bfloat16(v);
    __nv_bfloat16_raw raw = h;
    return raw.x;
}
__device__ __forceinline__ float bf16val(float v) {
    return __bfloat162float(__float2bfloat16(v));
}
__device__ __forceinline__ uint32_t prmt0(uint32_t a, uint32_t sel) {
    uint32_t d, z = 0;
    asm("prmt.b32 %0, %1, %2, %3;" : "=r"(d) : "r"(a), "r"(z), "r"(sel));
    return d;
}
__device__ __forceinline__ uint32_t prmt2(uint32_t a, uint32_t b, uint32_t sel) {
    uint32_t d;
    asm("prmt.b32 %0, %1, %2, %3;" : "=r"(d) : "r"(a), "r"(b), "r"(sel));
    return d;
}

__device__ __forceinline__ void mma16816(float c[4], const uint32_t a[4],
                                         const uint32_t b[2]) {
    asm volatile(
        "mma.sync.aligned.m16n8k16.row.col.f32.bf16.bf16.f32 "
        "{%0,%1,%2,%3}, {%4,%5,%6,%7}, {%8,%9}, {%0,%1,%2,%3};"
        : "+f"(c[0]), "+f"(c[1]), "+f"(c[2]), "+f"(c[3])
        : "r"(a[0]), "r"(a[1]), "r"(a[2]), "r"(a[3]), "r"(b[0]), "r"(b[1]));
}

// ================= tensor-core GEMM via mma.sync (bf16 hi/lo 3-product) ====
#define KP 104  // bf16 pitch

template<int NG>
__global__ __launch_bounds__(256) void tmma_gemm(
    const float* __restrict__ Xin, const float* __restrict__ Win,
    const float* __restrict__ bias, float* __restrict__ Oout)
{
    extern __shared__ __align__(16) uint16_t sm[];
    uint16_t* sbh = sm;                       // B hi [128][KP]
    uint16_t* sbl = sm + 128 * KP;            // B lo
    uint16_t* sah = sm + 2 * 128 * KP;        // A hi [96][KP]
    uint16_t* sal = sm + 2 * 128 * KP + 96 * KP;

    const int tid  = threadIdx.x;
    const int warp = tid >> 5;
    const int l    = tid & 31;
    const int b    = blockIdx.z;
    const long n0  = (long)blockIdx.x * 128;

    const float* Xb; const float* Wb; float* Ob;
    if constexpr (NG == 3) {
        Xb = Xin + (long)b * C * HWPIX;
        Wb = Win;
        Ob = g_qkv + (long)b * C3 * HWPIX;
    } else {
        Xb = g_dw + ((long)b * C3 + 192) * HWPIX;   // v channels (packed uint32)
        Wb = g_M + (long)b * C * C;
        Ob = Oout + (long)b * C * HWPIX;
    }

    // ---- B tile: X[k][px] -> smem [px][k] bf16 hi/lo ----
    {
        const int px = tid & 127;
        const int kh = tid >> 7;
        if constexpr (NG == 3) {
            for (int k2 = kh; k2 < 48; k2 += 2) {
                const int k = k2 * 2;
                float v0 = Xb[(long)k * HWPIX + n0 + px];
                float v1 = Xb[(long)(k + 1) * HWPIX + n0 + px];
                float h0 = bf16val(v0);
                float h1 = bf16val(v1);
                *(uint32_t*)&sbh[px * KP + k] = packbf(v0, v1);
                *(uint32_t*)&sbl[px * KP + k] = packbf(v0 - h0, v1 - h1);
            }
        } else {
            const uint32_t* Xp = (const uint32_t*)Xb;
            for (int k2 = kh; k2 < 48; k2 += 2) {
                const int k = k2 * 2;
                uint32_t w0 = Xp[(long)k * HWPIX + n0 + px];
                uint32_t w1 = Xp[(long)(k + 1) * HWPIX + n0 + px];
                *(uint32_t*)&sbh[px * KP + k] = prmt2(w0, w1, 0x5410u);
                *(uint32_t*)&sbl[px * KP + k] = prmt2(w0, w1, 0x7632u);
            }
        }
    }

    const int wpx = warp * 16;
    const int lr = l >> 2;
    const int lc = (l & 3) * 2;

    for (int g = 0; g < NG; g++) {
        __syncthreads();
        const float* Wg = Wb + (long)g * 96 * 96;
        for (int i = tid; i < 96 * 96; i += 256) {
            int m = i / 96, k = i - m * 96;
            float w = Wg[i];
            sah[m * KP + k] = bf16bits(w);
            sal[m * KP + k] = bf16bits(w - bf16val(w));
        }
        __syncthreads();

        float c[6][2][4];
#pragma unroll
        for (int mt = 0; mt < 6; mt++)
#pragma unroll
            for (int nt = 0; nt < 2; nt++)
#pragma unroll
                for (int j = 0; j < 4; j++) c[mt][nt][j] = 0.f;

#pragma unroll
        for (int s = 0; s < 6; s++) {
            const int k0 = s * 16;
            uint32_t bh[2][2], bl[2][2];
#pragma unroll
            for (int nt = 0; nt < 2; nt++) {
                const int n = wpx + nt * 8 + lr;
                bh[nt][0] = *(const uint32_t*)&sbh[n * KP + k0 + lc];
                bh[nt][1] = *(const uint32_t*)&sbh[n * KP + k0 + lc + 8];
                bl[nt][0] = *(const uint32_t*)&sbl[n * KP + k0 + lc];
                bl[nt][1] = *(const uint32_t*)&sbl[n * KP + k0 + lc + 8];
            }
#pragma unroll
            for (int mt = 0; mt < 6; mt++) {
                const int r = mt * 16 + lr;
                uint32_t ah[4], al[4];
                ah[0] = *(const uint32_t*)&sah[r * KP + k0 + lc];
                ah[1] = *(const uint32_t*)&sah[(r + 8) * KP + k0 + lc];
                ah[2] = *(const uint32_t*)&sah[r * KP + k0 + lc + 8];
                ah[3] = *(const uint32_t*)&sah[(r + 8) * KP + k0 + lc + 8];
                al[0] = *(const uint32_t*)&sal[r * KP + k0 + lc];
                al[1] = *(const uint32_t*)&sal[(r + 8) * KP + k0 + lc];
                al[2] = *(const uint32_t*)&sal[r * KP + k0 + lc + 8];
                al[3] = *(const uint32_t*)&sal[(r + 8) * KP + k0 + lc + 8];
#pragma unroll
                for (int nt = 0; nt < 2; nt++) {
                    mma16816(c[mt][nt], ah, bh[nt]);
                    mma16816(c[mt][nt], ah, bl[nt]);
                    mma16816(c[mt][nt], al, bh[nt]);
                }
            }
        }

#pragma unroll
        for (int mt = 0; mt < 6; mt++) {
#pragma unroll
            for (int nt = 0; nt < 2; nt++) {
                const int ch0 = g * 96 + mt * 16 + lr;
                const long px = n0 + wpx + nt * 8 + lc;
                float b0 = __ldg(&bias[ch0]);
                float b1 = __ldg(&bias[ch0 + 8]);
                float2 v0 = { c[mt][nt][0] + b0, c[mt][nt][1] + b0 };
                float2 v1 = { c[mt][nt][2] + b1, c[mt][nt][3] + b1 };
                *(float2*)&Ob[(long)ch0 * HWPIX + px] = v0;
                *(float2*)&Ob[(long)(ch0 + 8) * HWPIX + px] = v1;
            }
        }
    }
}

// ---------------- K0: zero small accumulators ----------------
__global__ void zero_small() {
    int i = blockIdx.x * blockDim.x + threadIdx.x;
    if (i < B * HEADS * HC * HC) g_G[i] = 0.f;
    if (i < B * C) { g_qn[i] = 0.f; g_kn[i] = 0.f; }
}

// ---------------- K2: vectorized 3x3 depthwise conv (4 px/thread) ----------
// grid (8 ybands, 288 ch, 4 b), block (64,4). Thread: 4 cols x 8 rows rolling.
// All outputs packed {bf16 hi, bf16 lo} uint32. q/k also accumulate norms.
__global__ __launch_bounds__(256) void dwconv(
    const float* __restrict__ dw_w, const float* __restrict__ dw_b)
{
    const int tx = threadIdx.x;         // 0..63
    const int ty = threadIdx.y;         // 0..3
    const int ch = blockIdx.y;
    const int b  = blockIdx.z;
    const int col0 = tx * 4;
    const float* P = g_qkv + ((long)(b * C3 + ch)) * HWPIX;
    uint32_t*    O = (uint32_t*)(g_dw + ((long)(b * C3 + ch)) * HWPIX);

    float w[9];
#pragma unroll
    for (int t = 0; t < 9; t++) w[t] = __ldg(&dw_w[ch * 9 + t]);
    const float bias = __ldg(&dw_b[ch]);

    const int y0 = blockIdx.x * 32 + ty * 8;

    float A[6], Bw[6], Cw[6];
    auto loadrow = [&](int y, float* v) {
        if ((unsigned)y < 256u) {
            const float* row = P + y * WW + col0;
            float4 m = *(const float4*)row;
            v[0] = (col0 > 0)   ? __ldg(row - 1) : 0.f;
            v[1] = m.x; v[2] = m.y; v[3] = m.z; v[4] = m.w;
            v[5] = (col0 < 252) ? __ldg(row + 4) : 0.f;
        } else {
#pragma unroll
            for (int j = 0; j < 6; j++) v[j] = 0.f;
        }
    };
    loadrow(y0 - 1, A);
    loadrow(y0,     Bw);

    float ss = 0.f;
#pragma unroll
    for (int dy = 0; dy < 8; dy++) {
        loadrow(y0 + dy + 1, Cw);
        uint32_t pk[4];
#pragma unroll
        for (int j = 0; j < 4; j++) {
            float o = bias
                + w[0] * A[j]  + w[1] * A[j + 1]  + w[2] * A[j + 2]
                + w[3] * Bw[j] + w[4] * Bw[j + 1] + w[5] * Bw[j + 2]
                + w[6] * Cw[j] + w[7] * Cw[j + 1] + w[8] * Cw[j + 2];
            if (ch < 192) ss += o * o;
            pk[j] = packbf(o, o - bf16val(o));
        }
        *(uint4*)&O[(y0 + dy) * WW + col0] = *(uint4*)pk;
#pragma unroll
        for (int j = 0; j < 6; j++) { A[j] = Bw[j]; Bw[j] = Cw[j]; }
    }

    if (ch < 192) {
        const int tid = ty * 64 + tx;
#pragma unroll
        for (int o = 16; o; o >>= 1) ss += __shfl_down_sync(0xffffffffu, ss, o);
        __shared__ float red[8];
        if ((tid & 31) == 0) red[tid >> 5] = ss;
        __syncthreads();
        if (tid == 0) {
            float t = 0.f;
#pragma unroll
            for (int i = 0; i < 8; i++) t += red[i];
            float* dst = (ch < 96) ? &g_qn[b * C + ch] : &g_kn[b * C + ch - 96];
            atomicAdd(dst, t);
        }
    }
}

// ---------------- K3: Gram via mma.sync on packed {hi,lo} words -------------
// grid (64, 3, 4), block 256. Chunk = 1024 px, 4 slices of 256 px.
#define GPITCH 260
__global__ __launch_bounds__(256) void gram_mma()
{
    extern __shared__ uint32_t gsm[];
    uint32_t* qs = gsm;
    uint32_t* ks = gsm + 32 * GPITCH;
    float* red = (float*)gsm;          // reused after compute: [8][1024]

    const int chunk = blockIdx.x, h = blockIdx.y, b = blockIdx.z;
    const uint32_t* qg = (const uint32_t*)g_dw + ((long)(b * C3 + h * HC)) * HWPIX;
    const uint32_t* kg = (const uint32_t*)g_dw + ((long)(b * C3 + 96 + h * HC)) * HWPIX;
    const int tid = threadIdx.x, w = tid >> 5, l = tid & 31;
    const int lr = l >> 2, lq = l & 3;

    float c[2][4][4];
#pragma unroll
    for (int mt = 0; mt < 2; mt++)
#pragma unroll
        for (int nt = 0; nt < 4; nt++)
#pragma unroll
            for (int j = 0; j < 4; j++) c[mt][nt][j] = 0.f;

    const long base = (long)chunk * 1024;
    for (int s = 0; s < 4; s++) {
        const long n = base + s * 256;
        __syncthreads();
#pragma unroll
        for (int e = 0; e < 8; e++) {
            int i4 = e * 256 + tid;
            int ch = i4 >> 6, p4 = (i4 & 63) * 4;
            *(uint4*)&qs[ch * GPITCH + p4] = *(const uint4*)&qg[(long)ch * HWPIX + n + p4];
            *(uint4*)&ks[ch * GPITCH + p4] = *(const uint4*)&kg[(long)ch * HWPIX + n + p4];
        }
        __syncthreads();

        const int pxw = w * 32;
#pragma unroll
        for (int st = 0; st < 4; st++) {
            const int pxb = pxw + st * 8;
            uint32_t bh[4][2], bl[4][2];
#pragma unroll
            for (int nt = 0; nt < 4; nt++) {
                uint32_t r0 = ks[(nt * 8 + lr) * GPITCH + pxb + lq];
                uint32_t r1 = ks[(nt * 8 + lr) * GPITCH + pxb + 4 + lq];
                bh[nt][0] = prmt0(r0, 0x1010u); bl[nt][0] = prmt0(r0, 0x4432u);
                bh[nt][1] = prmt0(r1, 0x1010u); bl[nt][1] = prmt0(r1, 0x4432u);
            }
#pragma unroll
            for (int mt = 0; mt < 2; mt++) {
                uint32_t a[4];
                a[0] = qs[(mt * 16 + lr) * GPITCH + pxb + lq];
                a[1] = qs[(mt * 16 + 8 + lr) * GPITCH + pxb + lq];
                a[2] = qs[(mt * 16 + lr) * GPITCH + pxb + 4 + lq];
                a[3] = qs[(mt * 16 + 8 + lr) * GPITCH + pxb + 4 + lq];
#pragma unroll
                for (int nt = 0; nt < 4; nt++) {
                    mma16816(c[mt][nt], a, bh[nt]);
                    mma16816(c[mt][nt], a, bl[nt]);
                }
            }
        }
    }

    __syncthreads();
#pragma unroll
    for (int mt = 0; mt < 2; mt++)
#pragma unroll
        for (int nt = 0; nt < 4; nt++)
#pragma unroll
            for (int j = 0; j < 4; j++) {
                int row = mt * 16 + lr + ((j >> 1) << 3);
                int cl  = nt * 8 + lq * 2 + (j & 1);
                red[w * 1024 + row * 32 + cl] = c[mt][nt][j];
            }
    __syncthreads();
    float* Gp = g_G + (long)(b * HEADS + h) * HC * HC;
    for (int i = tid; i < 1024; i += 256) {
        float sum = 0.f;
#pragma unroll
        for (int ww = 0; ww < 8; ww++) sum += red[ww * 1024 + i];
        atomicAdd(&Gp[i], sum);
    }
}

// ---------------- K3b: softmax(G / (||q|| ||k||)) -> d_out tail ------------
__global__ void attn_softmax(float* __restrict__ out)
{
    const int blk = blockIdx.x;
    const int b = blk / 3, h = blk % 3;
    const int c = threadIdx.x;
    float nq = fmaxf(sqrtf(g_qn[b * C + h * HC + c]), 1e-12f);

    float v[32];
#pragma unroll
    for (int d = 0; d < 32; d++) {
        float nk = fmaxf(sqrtf(g_kn[b * C + h * HC + d]), 1e-12f);
        v[d] = g_G[(blk * HC + c) * HC + d] / (nq * nk);
    }
    float m = -1e30f;
#pragma unroll
    for (int d = 0; d < 32; d++) m = fmaxf(m, v[d]);
    float s = 0.f;
#pragma unroll
    for (int d = 0; d < 32; d++) { v[d] = expf(v[d] - m); s += v[d]; }
    float inv = 1.f / s;
    float* ap = out + OUT_ELEMS + (long)blk * (HC * HC) + c * HC;
#pragma unroll
    for (int d = 0; d < 32; d++) ap[d] = v[d] * inv;
}

// ---------------- K3c: M[b] = proj_w @ blockdiag(attn[b]) ----------------
__global__ void make_M(const float* __restrict__ proj_w, const float* __restrict__ out)
{
    const int b = blockIdx.x, tid = threadIdx.x;
    const float* attn = out + OUT_ELEMS;
#pragma unroll 4
    for (int e = 0; e < 36; e++) {
        int idx = e * 256 + tid;
        int o = idx / 96, g = idx % 96;
        int h = g >> 5, d = g & 31;
        const float* arow = attn + (long)(b * HEADS + h) * (HC * HC) + d;
        const float* prow = proj_w + o * 96 + h * HC;
        float s = 0.f;
#pragma unroll
        for (int cc = 0; cc < 32; cc++) s += prow[cc] * arow[cc * 32];
        g_M[(long)b * C * C + idx] = s;
    }
}

// ---------------- launch ----------------
extern "C" void kernel_launch(void* const* d_in, const int* in_sizes, int n_in,
                              void* d_out, int out_size)
{
    const float* x      = (const float*)d_in[0];
    const float* qkv_w  = (const float*)d_in[1];
    const float* qkv_b  = (const float*)d_in[2];
    const float* dw_w   = (const float*)d_in[3];
    const float* dw_b   = (const float*)d_in[4];
    const float* proj_w = (const float*)d_in[5];
    const float* proj_b = (const float*)d_in[6];
    float* out = (float*)d_out;

    const int smem_gemm = (2 * 128 * KP + 2 * 96 * KP) * 2;   // 93,184 B
    const int smem_gram = 2 * 32 * GPITCH * 4;                // 66,560 B
    cudaFuncSetAttribute(tmma_gemm<3>, cudaFuncAttributeMaxDynamicSharedMemorySize, smem_gemm);
    cudaFuncSetAttribute(tmma_gemm<1>, cudaFuncAttributeMaxDynamicSharedMemorySize, smem_gemm);
    cudaFuncSetAttribute(gram_mma,     cudaFuncAttributeMaxDynamicSharedMemorySize, smem_gram);

    zero_small<<<48, 256>>>();
    tmma_gemm<3><<<dim3(512, 1, B), 256, smem_gemm>>>(x, qkv_w, qkv_b, nullptr);
    dwconv<<<dim3(8, C3, B), dim3(64, 4)>>>(dw_w, dw_b);
    gram_mma<<<dim3(64, HEADS, B), 256, smem_gram>>>();
    attn_softmax<<<12, 32>>>(out);
    make_M<<<B, 256>>>(proj_w, out);
    tmma_gemm<1><<<dim3(512, 1, B), 256, smem_gemm>>>(nullptr, nullptr, proj_b, out);
}